// round 13
// baseline (speedup 1.0000x reference)
#include <cuda_runtime.h>
#include <stdint.h>

#define QW    8          // queries per block-chunk (1 per warp; 256-thread blocks)
#define QCAP  96         // query-list capacity per home cell
#define NHC   343        // 7^3 home cells (queries outside go to overflow path)
#define NMAP  1536
#define CAP   192        // candidate buffer per query
#define KMAX  32
#define MMAX  32768
#define GC    27         // grid cells per axis (1728/64)
#define NC    (GC*GC*GC)
#define CSH   6          // log2(cell size 64)
#define BCAP  32         // point bucket capacity per cell
#define NEAR2 4096       // 64^2: any point outside cheb<=1 cube has d2 > NEAR2
#define PMAX  (27*BCAP)  // 864: max staged points per block

// ---- device scratch (no allocs allowed) ----
struct Scratch {
    int ovcnt;                       // point-bucket overflow count
    int qovcnt;                      // query overflow count
    int cellcnt[NC];
    int qbcnt[NHC];
};
__device__ Scratch g_scr;            // zeroed by one cudaMemsetAsync per call
__device__ int   g_tot;              // number of mapped (cell,chunk) blocks
__device__ int   g_map[NMAP];        // block -> cell | chunk<<16
__device__ uint2 g_pts[NC * BCAP];   // .x = x|y<<16, .y = z|idx<<16
__device__ uint2 g_ov[MMAX];
__device__ int   g_qlist[NHC * QCAP];
__device__ int   g_qov[MMAX];

__device__ __forceinline__ int cell_of(int x, int y, int z) {
    return (x >> CSH) + GC * (y >> CSH) + GC * GC * (z >> CSH);
}

// ---- build: bin points into cell buckets AND queries into home cells ----
__global__ void build_kernel(const int* __restrict__ mid, const int* __restrict__ low,
                             const int* __restrict__ qc, int M1, int M, int N) {
    int i = blockIdx.x * blockDim.x + threadIdx.x;
    if (i < M) {
        const int* s = (i < M1) ? (mid + 3 * i) : (low + 3 * (i - M1));
        int x = s[0], y = s[1], z = s[2];
        int c = cell_of(x, y, z);
        uint2 pt = make_uint2((unsigned)x | ((unsigned)y << 16),
                              (unsigned)z | ((unsigned)i << 16));
        int pos = atomicAdd(&g_scr.cellcnt[c], 1);
        if (pos < BCAP) g_pts[c * BCAP + pos] = pt;
        else            g_ov[atomicAdd(&g_scr.ovcnt, 1)] = pt;
    }
    if (i < N) {
        int cx = qc[3 * i] >> CSH, cy = qc[3 * i + 1] >> CSH, cz = qc[3 * i + 2] >> CSH;
        if ((unsigned)cx < 7u && (unsigned)cy < 7u && (unsigned)cz < 7u) {
            int h = cx + 7 * cy + 49 * cz;
            int pos = atomicAdd(&g_scr.qbcnt[h], 1);
            if (pos < QCAP) g_qlist[h * QCAP + pos] = i;
            else            g_qov[atomicAdd(&g_scr.qovcnt, 1)] = i;
        } else {
            g_qov[atomicAdd(&g_scr.qovcnt, 1)] = i;
        }
    }
}

// ---- 1-block scan: build block -> (cell, chunk) map ----
__global__ void map_kernel() {
    __shared__ int s[512];
    int t = threadIdx.x;
    int c = 0;
    if (t < NHC) c = (min(g_scr.qbcnt[t], QCAP) + QW - 1) / QW;
    s[t] = c;
    __syncthreads();
    for (int off = 1; off < 512; off <<= 1) {
        int v = (t >= off) ? s[t - off] : 0;
        __syncthreads();
        s[t] += v;
        __syncthreads();
    }
    int excl = (t == 0) ? 0 : s[t - 1];
    if (t < NHC)
        for (int j = 0; j < c; j++) g_map[excl + j] = t | (j << 16);
    if (t == NHC - 1) g_tot = s[t];
}

// Exact k-th select + compact (keeps all ties). Warp-uniform cnt update.
__device__ __forceinline__ int warp_prune(uint2* buf, int& cnt, int k, int lane) {
    const unsigned FULL = 0xffffffffu;
    unsigned d2r[CAP / 32], idr[CAP / 32];
#pragma unroll
    for (int s = 0; s < CAP / 32; s++) {
        int i = s * 32 + lane;
        uint2 e = (i < cnt) ? buf[i] : make_uint2(0x7fffffffu, 0u);
        d2r[s] = e.x; idr[s] = e.y;
    }
    unsigned mx = 0;
#pragma unroll
    for (int s = 0; s < CAP / 32; s++) {
        int i = s * 32 + lane;
        if (i < cnt) mx = max(mx, d2r[s]);
    }
    unsigned lo = 0, hi = __reduce_max_sync(FULL, mx);
    while (lo < hi) {
        unsigned mid = (lo + hi) >> 1;
        int c = 0;
#pragma unroll
        for (int s = 0; s < CAP / 32; s++) c += (d2r[s] <= mid) ? 1 : 0;
        c = __reduce_add_sync(FULL, c);
        if (c >= k) hi = mid; else lo = mid + 1;
    }
    unsigned T = lo;
    int base = 0;
#pragma unroll
    for (int s = 0; s < CAP / 32; s++) {
        bool keep = (d2r[s] <= T);
        unsigned m = __ballot_sync(FULL, keep);
        if (keep) buf[base + __popc(m & ((1u << lane) - 1u))] = make_uint2(d2r[s], idr[s]);
        base += __popc(m);
    }
    __syncwarp();
    cnt = base;
    return (int)T;
}

struct WarpSmem {
    uint2    buf[CAP];
    int      cbase[32];
    int      ccnt[32];
    int      pref[33];
    int      selidx[KMAX];
    unsigned seld2[KMAX];
    float    wt[KMAX];
};

// Balanced segment-union scan over gmem (fallback): appends dlo < d2 <= T.
__device__ __forceinline__ void scan_batch(int ccnt, int cbase, int dlo,
                                           int qx, int qy, int qz, WarpSmem& sm,
                                           int& cnt, int& T, int kk,
                                           int lane, unsigned lmlt) {
    const unsigned FULL = 0xffffffffu;
    int inc = ccnt;
#pragma unroll
    for (int off = 1; off < 32; off <<= 1) {
        int v = __shfl_up_sync(FULL, inc, off);
        if (lane >= off) inc += v;
    }
    int P = __shfl_sync(FULL, inc, 31);
    if (P == 0) return;
    if (lane == 0) sm.pref[0] = 0;
    sm.pref[lane + 1] = inc;
    sm.cbase[lane] = cbase - (inc - ccnt);
    __syncwarp();

    const int nb = (P + 31) >> 5;
    for (int it = 0; it < nb; it += 2) {
        int t2a = it * 32 + lane;
        int t2b = t2a + 32;
        bool va = (t2a < P), vb = (t2b < P);
        int ja = 0, jb = 0;
#pragma unroll
        for (int step = 16; step >= 1; step >>= 1) {
            if (sm.pref[ja + step] <= t2a) ja += step;
            if (sm.pref[jb + step] <= t2b) jb += step;
        }
        uint2 pa, pb;
        if (va) pa = g_pts[sm.cbase[ja] + t2a];
        if (vb) pb = g_pts[sm.cbase[jb] + t2b];
        int d2a = 0, d2b = 0;
        unsigned ia = 0, ib = 0;
        if (va) {
            int dx = qx - (int)(pa.x & 0xffffu);
            int dy = qy - (int)(pa.x >> 16);
            int dz = qz - (int)(pa.y & 0xffffu);
            d2a = dx * dx + dy * dy + dz * dz;
            ia = pa.y >> 16;
        }
        if (vb) {
            int dx = qx - (int)(pb.x & 0xffffu);
            int dy = qy - (int)(pb.x >> 16);
            int dz = qz - (int)(pb.y & 0xffffu);
            d2b = dx * dx + dy * dy + dz * dz;
            ib = pb.y >> 16;
        }
        bool ha = va && (d2a > dlo) && (d2a <= T);
        unsigned ma = __ballot_sync(FULL, ha);
        if (ha) sm.buf[cnt + __popc(ma & lmlt)] = make_uint2((unsigned)d2a, ia);
        cnt += __popc(ma);
        bool hb = vb && (d2b > dlo) && (d2b <= T);
        unsigned mb = __ballot_sync(FULL, hb);
        if (hb) sm.buf[cnt + __popc(mb & lmlt)] = make_uint2((unsigned)d2b, ib);
        cnt += __popc(mb);
        if (cnt > CAP - 64) T = min(T, warp_prune(sm.buf, cnt, kk, lane));
    }
    __syncwarp();
}

// Fallback: exact kNN via ov list + expanding cells from gmem. If p1_ran, the
// buffer already holds ALL points with d2 <= NEAR2 exactly once (cube complete,
// no prune could have fired since cnt < kk <= 32): append only d2 > NEAR2 from
// the cube; shells are disjoint from the cube.
__device__ __forceinline__ void fallback_scan(WarpSmem& sm, int& cnt, bool p1_ran,
                                              int qx, int qy, int qz,
                                              int kk, int ov, int lane, unsigned lmlt) {
    const unsigned FULL = 0xffffffffu;
    const int qcx = min(max(qx >> CSH, 0), GC - 1);
    const int qcy = min(max(qy >> CSH, 0), GC - 1);
    const int qcz = min(max(qz >> CSH, 0), GC - 1);
    int T = 0x7fffffff;

    for (int b = 0; b < ov; b += 32) {
        int i = b + lane;
        bool valid = (i < ov);
        int d2 = 0; unsigned pidx = 0;
        if (valid) {
            uint2 p = g_ov[i];
            int dx = qx - (int)(p.x & 0xffffu);
            int dy = qy - (int)(p.x >> 16);
            int dz = qz - (int)(p.y & 0xffffu);
            d2 = dx * dx + dy * dy + dz * dz;
            pidx = p.y >> 16;
        }
        bool hit = valid && (d2 <= T);
        unsigned m = __ballot_sync(FULL, hit);
        if (hit) sm.buf[cnt + __popc(m & lmlt)] = make_uint2((unsigned)d2, pidx);
        cnt += __popc(m);
        if (cnt > CAP - 32) T = warp_prune(sm.buf, cnt, kk, lane);
    }

    const int dlo0 = p1_ran ? NEAR2 : -1;
    bool done = false;
    for (int s = 1; s < GC && !done; s++) {
        const int side = 2 * s + 1;
        const int ncube = side * side * side;
        const bool first = (s == 1);
        const int dlo = first ? dlo0 : -1;
        for (int b = 0; b < ncube; b += 32) {
            int t = b + lane;
            int ccnt = 0, cbase = 0;
            if (t < ncube) {
                int di = t % side - s;
                int r1 = t / side;
                int dj = r1 % side - s;
                int dk = r1 / side - s;
                int cheb = max(abs(di), max(abs(dj), abs(dk)));
                int ci = qcx + di, cj = qcy + dj, ck = qcz + dk;
                if ((first || cheb == s) && ci >= 0 && ci < GC && cj >= 0
                                         && cj < GC && ck >= 0 && ck < GC) {
                    int lx = ci << CSH, ly = cj << CSH, lz = ck << CSH;
                    int mdx = max(0, max(lx - qx, qx - (lx + 63)));
                    int mdy = max(0, max(ly - qy, qy - (ly + 63)));
                    int mdz = max(0, max(lz - qz, qz - (lz + 63)));
                    int md2 = mdx * mdx + mdy * mdy + mdz * mdz;
                    if (md2 <= T) {
                        int cell = ci + GC * cj + GC * GC * ck;
                        ccnt = min(g_scr.cellcnt[cell], BCAP);
                        cbase = cell * BCAP;
                    }
                }
            }
            scan_batch(ccnt, cbase, dlo, qx, qy, qz, sm, cnt, T, kk, lane, lmlt);
        }
        if (cnt >= kk) {
            T = warp_prune(sm.buf, cnt, kk, lane);
            int bnd = s << CSH;
            if (bnd * bnd >= T) done = true;
        }
    }
}

// Final exact top-k by composite key (d2, idx), weights, feature gather.
__device__ __forceinline__ void finish_query(WarpSmem& sm, int cnt, int kk, int q,
                                             const float* __restrict__ midf,
                                             const float* __restrict__ lowf,
                                             float* __restrict__ out,
                                             int M1, int D, int lane) {
    const unsigned FULL = 0xffffffffu;
    if (cnt > 64) warp_prune(sm.buf, cnt, kk, lane);
    const int kk2 = min(kk, cnt);
    {
        bool v0 = (lane < cnt), v1 = (lane + 32 < cnt);
        uint2 e0 = v0 ? sm.buf[lane]      : make_uint2(0u, 0u);
        uint2 e1 = v1 ? sm.buf[lane + 32] : make_uint2(0u, 0u);
        unsigned mxd2 = __reduce_max_sync(FULL, max(v0 ? e0.x : 0u, v1 ? e1.x : 0u));
        if (cnt <= 64 && mxd2 < (1u << 17)) {
            unsigned k0 = v0 ? ((e0.x << 15) | (e0.y & 0x7fffu)) : 0xffffffffu;
            unsigned k1 = v1 ? ((e1.x << 15) | (e1.y & 0x7fffu)) : 0xffffffffu;
            if (cnt <= 32) {
                int r0 = 0;
                for (int j = 0; j < 32; j++) {
                    unsigned a = __shfl_sync(FULL, k0, j);
                    r0 += (a < k0) ? 1 : 0;
                }
                if (v0 && r0 < kk2) { sm.selidx[r0] = (int)e0.y; sm.seld2[r0] = e0.x; }
            } else {
                int r0 = 0, r1 = 0;
                for (int j = 0; j < 32; j++) {
                    unsigned a = __shfl_sync(FULL, k0, j);
                    unsigned b = __shfl_sync(FULL, k1, j);
                    r0 += ((a < k0) ? 1 : 0) + ((b < k0) ? 1 : 0);
                    r1 += ((a < k1) ? 1 : 0) + ((b < k1) ? 1 : 0);
                }
                if (v0 && r0 < kk2) { sm.selidx[r0] = (int)e0.y; sm.seld2[r0] = e0.x; }
                if (v1 && r1 < kk2) { sm.selidx[r1] = (int)e1.y; sm.seld2[r1] = e1.x; }
            }
        } else {
            for (int i = lane; i < cnt; i += 32) {
                uint2 ei = sm.buf[i];
                int rk = 0;
                for (int j = 0; j < cnt; j++) {
                    uint2 ej = sm.buf[j];
                    rk += (ej.x < ei.x || (ej.x == ei.x && ej.y < ei.y)) ? 1 : 0;
                }
                if (rk < kk2) { sm.selidx[rk] = (int)ei.y; sm.seld2[rk] = ei.x; }
            }
        }
        __syncwarp();
    }

    float wj = 0.0f;
    if (lane < kk2) wj = 1.0f / (1.0f + sqrtf((float)sm.seld2[lane]));
    float tot = wj;
#pragma unroll
    for (int o = 16; o > 0; o >>= 1) tot += __shfl_xor_sync(FULL, tot, o);
    if (lane < kk2) sm.wt[lane] = wj / tot;
    __syncwarp();

    if (D == 128) {
        float4 acc = make_float4(0.f, 0.f, 0.f, 0.f);
        int j = 0;
        for (; j + 4 <= kk2; j += 4) {
            const float* f[4];
            float wt[4];
#pragma unroll
            for (int u = 0; u < 4; u++) {
                int si = sm.selidx[j + u];
                wt[u] = sm.wt[j + u];
                f[u] = (si < M1) ? (midf + (size_t)si * 128)
                                 : (lowf + (size_t)(si - M1) * 128);
            }
            float4 v0 = *(const float4*)(f[0] + lane * 4);
            float4 v1 = *(const float4*)(f[1] + lane * 4);
            float4 v2 = *(const float4*)(f[2] + lane * 4);
            float4 v3 = *(const float4*)(f[3] + lane * 4);
            acc.x += wt[0] * v0.x + wt[1] * v1.x + wt[2] * v2.x + wt[3] * v3.x;
            acc.y += wt[0] * v0.y + wt[1] * v1.y + wt[2] * v2.y + wt[3] * v3.y;
            acc.z += wt[0] * v0.z + wt[1] * v1.z + wt[2] * v2.z + wt[3] * v3.z;
            acc.w += wt[0] * v0.w + wt[1] * v1.w + wt[2] * v2.w + wt[3] * v3.w;
        }
        for (; j < kk2; j++) {
            int   si = sm.selidx[j];
            float wt = sm.wt[j];
            const float* f = (si < M1) ? (midf + (size_t)si * 128)
                                       : (lowf + (size_t)(si - M1) * 128);
            float4 v = *(const float4*)(f + lane * 4);
            acc.x += wt * v.x; acc.y += wt * v.y;
            acc.z += wt * v.z; acc.w += wt * v.w;
        }
        *(float4*)(out + (size_t)q * 128 + lane * 4) = acc;
    } else {
        for (int d = lane; d < D; d += 32) {
            float a = 0.f;
            for (int j = 0; j < kk2; j++) {
                int   si = sm.selidx[j];
                float wt = sm.wt[j];
                const float* f = (si < M1) ? (midf + (size_t)si * D)
                                           : (lowf + (size_t)(si - M1) * D);
                a += wt * f[d];
            }
            out[(size_t)q * D + d] = a;
        }
    }
}

__global__ __launch_bounds__(256, 6)
void knn_query_kernel(const int* __restrict__ qc,
                      const float* __restrict__ midf,
                      const float* __restrict__ lowf,
                      const int* __restrict__ kp,
                      float* __restrict__ out,
                      int N, int M1, int D) {
    __shared__ uint2    s_pts[PMAX];
    __shared__ int      s_cb[32], s_cc[32], s_pp[33];
    __shared__ WarpSmem sm8[QW];

    const unsigned FULL = 0xffffffffu;
    const int tid = threadIdx.x;
    const int w = tid >> 5;
    const int lane = tid & 31;
    const unsigned lmlt = (1u << lane) - 1u;
    const int kk = kp ? min(*kp, KMAX) : 24;
    const int ov = g_scr.ovcnt;
    const int tot = g_tot;
    WarpSmem& sm = sm8[w];

    const int b = blockIdx.x;
    if (b < tot) {
        // ---- shared-neighborhood path ----
        int mc = g_map[b];
        int cell = mc & 0xffff, chunk = mc >> 16;
        int hcx = cell % 7, hcy = (cell / 7) % 7, hcz = cell / 49;
        int qn = min(min(g_scr.qbcnt[cell], QCAP) - chunk * QW, QW);

        // stage 27-cell neighborhood into smem (whole block)
        if (tid < 32) {
            int cc = 0, cb = 0;
            if (tid < 27) {
                int ci = hcx + tid % 3 - 1;
                int cj = hcy + (tid / 3) % 3 - 1;
                int ck = hcz + tid / 9 - 1;
                if (ci >= 0 && ci < GC && cj >= 0 && cj < GC && ck >= 0 && ck < GC) {
                    int cl = ci + GC * cj + GC * GC * ck;
                    cc = min(g_scr.cellcnt[cl], BCAP);
                    cb = cl * BCAP;
                }
            }
            s_cb[tid] = cb;
            s_cc[tid] = cc;
            int inc = cc;
#pragma unroll
            for (int off = 1; off < 32; off <<= 1) {
                int v = __shfl_up_sync(FULL, inc, off);
                if (tid >= off) inc += v;
            }
            if (tid == 0) s_pp[0] = 0;
            s_pp[tid + 1] = inc;
        }
        __syncthreads();
        const int P = s_pp[32];
        for (int idx = tid; idx < P; idx += 256) {
            int j = 0;
#pragma unroll
            for (int st = 16; st >= 1; st >>= 1)
                if (s_pp[j + st] <= idx) j += st;
            s_pts[idx] = g_pts[s_cb[j] + idx - s_pp[j]];
        }
        __syncthreads();

        if (w < qn) {
            int q = g_qlist[cell * QCAP + chunk * QW + w];
            int qx = qc[3 * q], qy = qc[3 * q + 1], qz = qc[3 * q + 2];
            int cnt = 0;
            bool p1_ran = false;
            if (ov == 0) {
                // scan staged points; all pts outside cube have d2 > NEAR2
                p1_ran = true;
                int T1 = NEAR2;
                for (int t0 = 0; t0 < P; t0 += 32) {
                    int t = t0 + lane;
                    bool v = (t < P);
                    int d2 = 0; unsigned pidx = 0;
                    if (v) {
                        uint2 p = s_pts[t];
                        int dx = qx - (int)(p.x & 0xffffu);
                        int dy = qy - (int)(p.x >> 16);
                        int dz = qz - (int)(p.y & 0xffffu);
                        d2 = dx * dx + dy * dy + dz * dz;
                        pidx = p.y >> 16;
                    }
                    bool hit = v && (d2 <= T1);
                    unsigned m = __ballot_sync(FULL, hit);
                    if (hit) sm.buf[cnt + __popc(m & lmlt)] = make_uint2((unsigned)d2, pidx);
                    cnt += __popc(m);
                    if (cnt > CAP - 32) T1 = min(T1, warp_prune(sm.buf, cnt, kk, lane));
                }
            }
            if (cnt < kk)
                fallback_scan(sm, cnt, p1_ran, qx, qy, qz, kk, ov, lane, lmlt);
            finish_query(sm, cnt, kk, q, midf, lowf, out, M1, D, lane);
        }
    } else {
        // ---- overflow queries: full gmem fallback path ----
        int ovq = g_scr.qovcnt;
        int qi = (b - tot) * QW + w;
        if (qi < ovq) {
            int q = g_qov[qi];
            int qx = qc[3 * q], qy = qc[3 * q + 1], qz = qc[3 * q + 2];
            int cnt = 0;
            fallback_scan(sm, cnt, false, qx, qy, qz, kk, ov, lane, lmlt);
            finish_query(sm, cnt, kk, q, midf, lowf, out, M1, D, lane);
        }
    }
}

extern "C" void kernel_launch(void* const* d_in, const int* in_sizes, int n_in,
                              void* d_out, int out_size) {
    const int*   qcoor = (const int*)d_in[0];
    const int*   midc  = (const int*)d_in[1];
    const int*   lowc  = (const int*)d_in[2];
    const float* midf  = (const float*)d_in[3];
    const float* lowf  = (const float*)d_in[4];
    const int*   kp    = (n_in >= 6) ? (const int*)d_in[5] : nullptr;

    const int N  = in_sizes[0] / 3;
    const int M1 = in_sizes[1] / 3;
    const int M2 = in_sizes[2] / 3;
    const int M  = M1 + M2;
    const int D  = (M1 > 0) ? in_sizes[3] / M1 : 128;

    void* scr = nullptr;
    cudaGetSymbolAddress(&scr, g_scr);             // host query, not a stream op
    cudaMemsetAsync(scr, 0, sizeof(Scratch));      // zero all counters

    const int mx = (M > N) ? M : N;
    build_kernel<<<(mx + 255) / 256, 256>>>(midc, lowc, qcoor, M1, M, N);
    map_kernel<<<1, 512>>>();

    // grid covers worst split between mapped chunks and overflow chunks:
    // tot <= NHC + N/QW, ovchunks <= ceil(N/QW); sum <= NHC + N/QW*2 + 2 is loose,
    // tight bound: tot + ovchunks <= NHC + (N_binned + N_ov)/QW + 2
    const int ngrid = NHC + (N + QW - 1) / QW + 2;
    knn_query_kernel<<<ngrid, 256>>>(qcoor, midf, lowf, kp, (float*)d_out, N, M1, D);
}

// round 14
// speedup vs baseline: 1.0528x; 1.0528x over previous
#include <cuda_runtime.h>
#include <stdint.h>

#define QW    8          // queries per block-chunk (1 per warp; 256-thread blocks)
#define QCAP  64         // query-list capacity per home cell
#define MAXCH 8          // max chunks per cell = QCAP/QW
#define NHC   343        // 7^3 home cells (queries outside go to overflow path)
#define CAP   192        // candidate buffer per query
#define KMAX  32
#define MMAX  32768
#define GC    27         // grid cells per axis (1728/64)
#define NC    (GC*GC*GC)
#define CSH   6          // log2(cell size 64)
#define BCAP  32         // point bucket capacity per cell
#define NEAR2 4096       // 64^2: any point outside cheb<=1 cube has d2 > NEAR2
#define PMAX  (27*BCAP)  // 864: max staged points per block

// ---- device scratch (no allocs allowed) ----
struct Scratch {
    int ovcnt;                       // point-bucket overflow count
    int qovcnt;                      // query overflow count
    int cellcnt[NC];
    int qbcnt[NHC];
};
__device__ Scratch g_scr;            // zeroed by one cudaMemsetAsync per call
__device__ uint2 g_pts[NC * BCAP];   // .x = x|y<<16, .y = z|idx<<16
__device__ uint2 g_ov[MMAX];
__device__ int   g_qlist[NHC * QCAP];
__device__ int   g_qov[MMAX];

__device__ __forceinline__ int cell_of(int x, int y, int z) {
    return (x >> CSH) + GC * (y >> CSH) + GC * GC * (z >> CSH);
}

// ---- build: bin points into cell buckets AND queries into home cells ----
__global__ void build_kernel(const int* __restrict__ mid, const int* __restrict__ low,
                             const int* __restrict__ qc, int M1, int M, int N) {
    int i = blockIdx.x * blockDim.x + threadIdx.x;
    if (i < M) {
        const int* s = (i < M1) ? (mid + 3 * i) : (low + 3 * (i - M1));
        int x = s[0], y = s[1], z = s[2];
        int c = cell_of(x, y, z);
        uint2 pt = make_uint2((unsigned)x | ((unsigned)y << 16),
                              (unsigned)z | ((unsigned)i << 16));
        int pos = atomicAdd(&g_scr.cellcnt[c], 1);
        if (pos < BCAP) g_pts[c * BCAP + pos] = pt;
        else            g_ov[atomicAdd(&g_scr.ovcnt, 1)] = pt;
    }
    if (i < N) {
        int cx = qc[3 * i] >> CSH, cy = qc[3 * i + 1] >> CSH, cz = qc[3 * i + 2] >> CSH;
        if ((unsigned)cx < 7u && (unsigned)cy < 7u && (unsigned)cz < 7u) {
            int h = cx + 7 * cy + 49 * cz;
            int pos = atomicAdd(&g_scr.qbcnt[h], 1);
            if (pos < QCAP) g_qlist[h * QCAP + pos] = i;
            else            g_qov[atomicAdd(&g_scr.qovcnt, 1)] = i;
        } else {
            g_qov[atomicAdd(&g_scr.qovcnt, 1)] = i;
        }
    }
}

// Exact k-th select + compact (keeps all ties). Warp-uniform cnt update.
__device__ __forceinline__ int warp_prune(uint2* buf, int& cnt, int k, int lane) {
    const unsigned FULL = 0xffffffffu;
    unsigned d2r[CAP / 32], idr[CAP / 32];
#pragma unroll
    for (int s = 0; s < CAP / 32; s++) {
        int i = s * 32 + lane;
        uint2 e = (i < cnt) ? buf[i] : make_uint2(0x7fffffffu, 0u);
        d2r[s] = e.x; idr[s] = e.y;
    }
    unsigned mx = 0;
#pragma unroll
    for (int s = 0; s < CAP / 32; s++) {
        int i = s * 32 + lane;
        if (i < cnt) mx = max(mx, d2r[s]);
    }
    unsigned lo = 0, hi = __reduce_max_sync(FULL, mx);
    while (lo < hi) {
        unsigned mid = (lo + hi) >> 1;
        int c = 0;
#pragma unroll
        for (int s = 0; s < CAP / 32; s++) c += (d2r[s] <= mid) ? 1 : 0;
        c = __reduce_add_sync(FULL, c);
        if (c >= k) hi = mid; else lo = mid + 1;
    }
    unsigned T = lo;
    int base = 0;
#pragma unroll
    for (int s = 0; s < CAP / 32; s++) {
        bool keep = (d2r[s] <= T);
        unsigned m = __ballot_sync(FULL, keep);
        if (keep) buf[base + __popc(m & ((1u << lane) - 1u))] = make_uint2(d2r[s], idr[s]);
        base += __popc(m);
    }
    __syncwarp();
    cnt = base;
    return (int)T;
}

struct WarpSmem {
    uint2    buf[CAP];
    int      cbase[32];
    int      ccnt[32];
    int      pref[33];
    int      selidx[KMAX];
    unsigned seld2[KMAX];
    float    wt[KMAX];
};

// Balanced segment-union scan over gmem (fallback): appends dlo < d2 <= T.
__device__ __forceinline__ void scan_batch(int ccnt, int cbase, int dlo,
                                           int qx, int qy, int qz, WarpSmem& sm,
                                           int& cnt, int& T, int kk,
                                           int lane, unsigned lmlt) {
    const unsigned FULL = 0xffffffffu;
    int inc = ccnt;
#pragma unroll
    for (int off = 1; off < 32; off <<= 1) {
        int v = __shfl_up_sync(FULL, inc, off);
        if (lane >= off) inc += v;
    }
    int P = __shfl_sync(FULL, inc, 31);
    if (P == 0) return;
    if (lane == 0) sm.pref[0] = 0;
    sm.pref[lane + 1] = inc;
    sm.cbase[lane] = cbase - (inc - ccnt);
    __syncwarp();

    const int nb = (P + 31) >> 5;
    for (int it = 0; it < nb; it += 2) {
        int t2a = it * 32 + lane;
        int t2b = t2a + 32;
        bool va = (t2a < P), vb = (t2b < P);
        int ja = 0, jb = 0;
#pragma unroll
        for (int step = 16; step >= 1; step >>= 1) {
            if (sm.pref[ja + step] <= t2a) ja += step;
            if (sm.pref[jb + step] <= t2b) jb += step;
        }
        uint2 pa, pb;
        if (va) pa = g_pts[sm.cbase[ja] + t2a];
        if (vb) pb = g_pts[sm.cbase[jb] + t2b];
        int d2a = 0, d2b = 0;
        unsigned ia = 0, ib = 0;
        if (va) {
            int dx = qx - (int)(pa.x & 0xffffu);
            int dy = qy - (int)(pa.x >> 16);
            int dz = qz - (int)(pa.y & 0xffffu);
            d2a = dx * dx + dy * dy + dz * dz;
            ia = pa.y >> 16;
        }
        if (vb) {
            int dx = qx - (int)(pb.x & 0xffffu);
            int dy = qy - (int)(pb.x >> 16);
            int dz = qz - (int)(pb.y & 0xffffu);
            d2b = dx * dx + dy * dy + dz * dz;
            ib = pb.y >> 16;
        }
        bool ha = va && (d2a > dlo) && (d2a <= T);
        unsigned ma = __ballot_sync(FULL, ha);
        if (ha) sm.buf[cnt + __popc(ma & lmlt)] = make_uint2((unsigned)d2a, ia);
        cnt += __popc(ma);
        bool hb = vb && (d2b > dlo) && (d2b <= T);
        unsigned mb = __ballot_sync(FULL, hb);
        if (hb) sm.buf[cnt + __popc(mb & lmlt)] = make_uint2((unsigned)d2b, ib);
        cnt += __popc(mb);
        if (cnt > CAP - 64) T = min(T, warp_prune(sm.buf, cnt, kk, lane));
    }
    __syncwarp();
}

// Fallback: exact kNN via ov list + expanding cells from gmem. If p1_ran, the
// buffer already holds ALL points with d2 <= NEAR2 exactly once (cube complete,
// cnt < kk <= 32 means no prune fired): append only d2 > NEAR2 from the cube;
// shells are disjoint from the cube.
__device__ __forceinline__ void fallback_scan(WarpSmem& sm, int& cnt, bool p1_ran,
                                              int qx, int qy, int qz,
                                              int kk, int ov, int lane, unsigned lmlt) {
    const unsigned FULL = 0xffffffffu;
    const int qcx = min(max(qx >> CSH, 0), GC - 1);
    const int qcy = min(max(qy >> CSH, 0), GC - 1);
    const int qcz = min(max(qz >> CSH, 0), GC - 1);
    int T = 0x7fffffff;

    for (int b = 0; b < ov; b += 32) {
        int i = b + lane;
        bool valid = (i < ov);
        int d2 = 0; unsigned pidx = 0;
        if (valid) {
            uint2 p = g_ov[i];
            int dx = qx - (int)(p.x & 0xffffu);
            int dy = qy - (int)(p.x >> 16);
            int dz = qz - (int)(p.y & 0xffffu);
            d2 = dx * dx + dy * dy + dz * dz;
            pidx = p.y >> 16;
        }
        bool hit = valid && (d2 <= T);
        unsigned m = __ballot_sync(FULL, hit);
        if (hit) sm.buf[cnt + __popc(m & lmlt)] = make_uint2((unsigned)d2, pidx);
        cnt += __popc(m);
        if (cnt > CAP - 32) T = warp_prune(sm.buf, cnt, kk, lane);
    }

    const int dlo0 = p1_ran ? NEAR2 : -1;
    bool done = false;
    for (int s = 1; s < GC && !done; s++) {
        const int side = 2 * s + 1;
        const int ncube = side * side * side;
        const bool first = (s == 1);
        const int dlo = first ? dlo0 : -1;
        for (int b = 0; b < ncube; b += 32) {
            int t = b + lane;
            int ccnt = 0, cbase = 0;
            if (t < ncube) {
                int di = t % side - s;
                int r1 = t / side;
                int dj = r1 % side - s;
                int dk = r1 / side - s;
                int cheb = max(abs(di), max(abs(dj), abs(dk)));
                int ci = qcx + di, cj = qcy + dj, ck = qcz + dk;
                if ((first || cheb == s) && ci >= 0 && ci < GC && cj >= 0
                                         && cj < GC && ck >= 0 && ck < GC) {
                    int lx = ci << CSH, ly = cj << CSH, lz = ck << CSH;
                    int mdx = max(0, max(lx - qx, qx - (lx + 63)));
                    int mdy = max(0, max(ly - qy, qy - (ly + 63)));
                    int mdz = max(0, max(lz - qz, qz - (lz + 63)));
                    int md2 = mdx * mdx + mdy * mdy + mdz * mdz;
                    if (md2 <= T) {
                        int cell = ci + GC * cj + GC * GC * ck;
                        ccnt = min(g_scr.cellcnt[cell], BCAP);
                        cbase = cell * BCAP;
                    }
                }
            }
            scan_batch(ccnt, cbase, dlo, qx, qy, qz, sm, cnt, T, kk, lane, lmlt);
        }
        if (cnt >= kk) {
            T = warp_prune(sm.buf, cnt, kk, lane);
            int bnd = s << CSH;
            if (bnd * bnd >= T) done = true;
        }
    }
}

// Final exact top-k by composite key (d2, idx), weights, feature gather.
__device__ __forceinline__ void finish_query(WarpSmem& sm, int cnt, int kk, int q,
                                             const float* __restrict__ midf,
                                             const float* __restrict__ lowf,
                                             float* __restrict__ out,
                                             int M1, int D, int lane) {
    const unsigned FULL = 0xffffffffu;
    if (cnt > 64) warp_prune(sm.buf, cnt, kk, lane);
    const int kk2 = min(kk, cnt);
    {
        bool v0 = (lane < cnt), v1 = (lane + 32 < cnt);
        uint2 e0 = v0 ? sm.buf[lane]      : make_uint2(0u, 0u);
        uint2 e1 = v1 ? sm.buf[lane + 32] : make_uint2(0u, 0u);
        unsigned mxd2 = __reduce_max_sync(FULL, max(v0 ? e0.x : 0u, v1 ? e1.x : 0u));
        if (cnt <= 64 && mxd2 < (1u << 17)) {
            unsigned k0 = v0 ? ((e0.x << 15) | (e0.y & 0x7fffu)) : 0xffffffffu;
            unsigned k1 = v1 ? ((e1.x << 15) | (e1.y & 0x7fffu)) : 0xffffffffu;
            if (cnt <= 32) {
                int r0 = 0;
                for (int j = 0; j < 32; j++) {
                    unsigned a = __shfl_sync(FULL, k0, j);
                    r0 += (a < k0) ? 1 : 0;
                }
                if (v0 && r0 < kk2) { sm.selidx[r0] = (int)e0.y; sm.seld2[r0] = e0.x; }
            } else {
                int r0 = 0, r1 = 0;
                for (int j = 0; j < 32; j++) {
                    unsigned a = __shfl_sync(FULL, k0, j);
                    unsigned b = __shfl_sync(FULL, k1, j);
                    r0 += ((a < k0) ? 1 : 0) + ((b < k0) ? 1 : 0);
                    r1 += ((a < k1) ? 1 : 0) + ((b < k1) ? 1 : 0);
                }
                if (v0 && r0 < kk2) { sm.selidx[r0] = (int)e0.y; sm.seld2[r0] = e0.x; }
                if (v1 && r1 < kk2) { sm.selidx[r1] = (int)e1.y; sm.seld2[r1] = e1.x; }
            }
        } else {
            for (int i = lane; i < cnt; i += 32) {
                uint2 ei = sm.buf[i];
                int rk = 0;
                for (int j = 0; j < cnt; j++) {
                    uint2 ej = sm.buf[j];
                    rk += (ej.x < ei.x || (ej.x == ei.x && ej.y < ei.y)) ? 1 : 0;
                }
                if (rk < kk2) { sm.selidx[rk] = (int)ei.y; sm.seld2[rk] = ei.x; }
            }
        }
        __syncwarp();
    }

    float wj = 0.0f;
    if (lane < kk2) wj = 1.0f / (1.0f + sqrtf((float)sm.seld2[lane]));
    float tot = wj;
#pragma unroll
    for (int o = 16; o > 0; o >>= 1) tot += __shfl_xor_sync(FULL, tot, o);
    if (lane < kk2) sm.wt[lane] = wj / tot;
    __syncwarp();

    if (D == 128) {
        float4 acc = make_float4(0.f, 0.f, 0.f, 0.f);
        int j = 0;
        for (; j + 4 <= kk2; j += 4) {
            const float* f[4];
            float wt[4];
#pragma unroll
            for (int u = 0; u < 4; u++) {
                int si = sm.selidx[j + u];
                wt[u] = sm.wt[j + u];
                f[u] = (si < M1) ? (midf + (size_t)si * 128)
                                 : (lowf + (size_t)(si - M1) * 128);
            }
            float4 v0 = *(const float4*)(f[0] + lane * 4);
            float4 v1 = *(const float4*)(f[1] + lane * 4);
            float4 v2 = *(const float4*)(f[2] + lane * 4);
            float4 v3 = *(const float4*)(f[3] + lane * 4);
            acc.x += wt[0] * v0.x + wt[1] * v1.x + wt[2] * v2.x + wt[3] * v3.x;
            acc.y += wt[0] * v0.y + wt[1] * v1.y + wt[2] * v2.y + wt[3] * v3.y;
            acc.z += wt[0] * v0.z + wt[1] * v1.z + wt[2] * v2.z + wt[3] * v3.z;
            acc.w += wt[0] * v0.w + wt[1] * v1.w + wt[2] * v2.w + wt[3] * v3.w;
        }
        for (; j < kk2; j++) {
            int   si = sm.selidx[j];
            float wt = sm.wt[j];
            const float* f = (si < M1) ? (midf + (size_t)si * 128)
                                       : (lowf + (size_t)(si - M1) * 128);
            float4 v = *(const float4*)(f + lane * 4);
            acc.x += wt * v.x; acc.y += wt * v.y;
            acc.z += wt * v.z; acc.w += wt * v.w;
        }
        *(float4*)(out + (size_t)q * 128 + lane * 4) = acc;
    } else {
        for (int d = lane; d < D; d += 32) {
            float a = 0.f;
            for (int j = 0; j < kk2; j++) {
                int   si = sm.selidx[j];
                float wt = sm.wt[j];
                const float* f = (si < M1) ? (midf + (size_t)si * D)
                                           : (lowf + (size_t)(si - M1) * D);
                a += wt * f[d];
            }
            out[(size_t)q * D + d] = a;
        }
    }
}

__global__ __launch_bounds__(256, 6)
void knn_query_kernel(const int* __restrict__ qc,
                      const float* __restrict__ midf,
                      const float* __restrict__ lowf,
                      const int* __restrict__ kp,
                      float* __restrict__ out,
                      int N, int M1, int D) {
    __shared__ uint2    s_pts[PMAX];
    __shared__ int      s_cb[32], s_pp[33];
    __shared__ WarpSmem sm8[QW];

    const unsigned FULL = 0xffffffffu;
    const int tid = threadIdx.x;
    const int w = tid >> 5;
    const int lane = tid & 31;
    const unsigned lmlt = (1u << lane) - 1u;
    const int kk = kp ? min(*kp, KMAX) : 24;
    const int ov = g_scr.ovcnt;
    WarpSmem& sm = sm8[w];

    const int b = blockIdx.x;
    if (b < NHC * MAXCH) {
        // ---- shared-neighborhood path; fixed (cell, chunk) addressing ----
        const int cell = b >> 3;          // MAXCH == 8
        const int chunk = b & 7;
        const int qn = min(min(g_scr.qbcnt[cell], QCAP) - chunk * QW, QW);
        if (qn <= 0) return;              // empty chunk: whole block exits pre-sync

        const int hcx = cell % 7, hcy = (cell / 7) % 7, hcz = cell / 49;

        // stage 27-cell neighborhood into smem (whole block)
        if (tid < 32) {
            int cc = 0, cb = 0;
            if (tid < 27) {
                int ci = hcx + tid % 3 - 1;
                int cj = hcy + (tid / 3) % 3 - 1;
                int ck = hcz + tid / 9 - 1;
                if (ci >= 0 && ci < GC && cj >= 0 && cj < GC && ck >= 0 && ck < GC) {
                    int cl = ci + GC * cj + GC * GC * ck;
                    cc = min(g_scr.cellcnt[cl], BCAP);
                    cb = cl * BCAP;
                }
            }
            s_cb[tid] = cb;
            int inc = cc;
#pragma unroll
            for (int off = 1; off < 32; off <<= 1) {
                int v = __shfl_up_sync(FULL, inc, off);
                if (tid >= off) inc += v;
            }
            if (tid == 0) s_pp[0] = 0;
            s_pp[tid + 1] = inc;
            s_cb[tid] = cb - (inc - cc);  // prefix-adjusted base
        }
        __syncthreads();
        const int P = s_pp[32];
        for (int idx = tid; idx < P; idx += 256) {
            int j = 0;
#pragma unroll
            for (int st = 16; st >= 1; st >>= 1)
                if (s_pp[j + st] <= idx) j += st;
            s_pts[idx] = g_pts[s_cb[j] + idx];
        }
        __syncthreads();

        if (w < qn) {
            int q = g_qlist[cell * QCAP + chunk * QW + w];
            int qx = qc[3 * q], qy = qc[3 * q + 1], qz = qc[3 * q + 2];
            int cnt = 0;
            bool p1_ran = false;
            if (ov == 0) {
                p1_ran = true;
                int T1 = NEAR2;
                for (int t0 = 0; t0 < P; t0 += 32) {
                    int t = t0 + lane;
                    bool v = (t < P);
                    int d2 = 0; unsigned pidx = 0;
                    if (v) {
                        uint2 p = s_pts[t];
                        int dx = qx - (int)(p.x & 0xffffu);
                        int dy = qy - (int)(p.x >> 16);
                        int dz = qz - (int)(p.y & 0xffffu);
                        d2 = dx * dx + dy * dy + dz * dz;
                        pidx = p.y >> 16;
                    }
                    bool hit = v && (d2 <= T1);
                    unsigned m = __ballot_sync(FULL, hit);
                    if (hit) sm.buf[cnt + __popc(m & lmlt)] = make_uint2((unsigned)d2, pidx);
                    cnt += __popc(m);
                    if (cnt > CAP - 32) T1 = min(T1, warp_prune(sm.buf, cnt, kk, lane));
                }
            }
            if (cnt < kk)
                fallback_scan(sm, cnt, p1_ran, qx, qy, qz, kk, ov, lane, lmlt);
            finish_query(sm, cnt, kk, q, midf, lowf, out, M1, D, lane);
        }
    } else {
        // ---- overflow queries: full gmem fallback path ----
        int ovq = g_scr.qovcnt;
        int qi = (b - NHC * MAXCH) * QW + w;
        if (qi < ovq) {
            int q = g_qov[qi];
            int qx = qc[3 * q], qy = qc[3 * q + 1], qz = qc[3 * q + 2];
            int cnt = 0;
            fallback_scan(sm, cnt, false, qx, qy, qz, kk, ov, lane, lmlt);
            finish_query(sm, cnt, kk, q, midf, lowf, out, M1, D, lane);
        }
    }
}

extern "C" void kernel_launch(void* const* d_in, const int* in_sizes, int n_in,
                              void* d_out, int out_size) {
    const int*   qcoor = (const int*)d_in[0];
    const int*   midc  = (const int*)d_in[1];
    const int*   lowc  = (const int*)d_in[2];
    const float* midf  = (const float*)d_in[3];
    const float* lowf  = (const float*)d_in[4];
    const int*   kp    = (n_in >= 6) ? (const int*)d_in[5] : nullptr;

    const int N  = in_sizes[0] / 3;
    const int M1 = in_sizes[1] / 3;
    const int M2 = in_sizes[2] / 3;
    const int M  = M1 + M2;
    const int D  = (M1 > 0) ? in_sizes[3] / M1 : 128;

    void* scr = nullptr;
    cudaGetSymbolAddress(&scr, g_scr);             // host query, not a stream op
    cudaMemsetAsync(scr, 0, sizeof(Scratch));      // zero all counters

    const int mx = (M > N) ? M : N;
    build_kernel<<<(mx + 255) / 256, 256>>>(midc, lowc, qcoor, M1, M, N);

    // fixed grid: 2744 mapped-chunk blocks + worst-case overflow blocks
    const int ngrid = NHC * MAXCH + (N + QW - 1) / QW;
    knn_query_kernel<<<ngrid, 256>>>(qcoor, midf, lowf, kp, (float*)d_out, N, M1, D);
}

// round 15
// speedup vs baseline: 1.1783x; 1.1192x over previous
#include <cuda_runtime.h>
#include <stdint.h>

#define QPB   4          // queries per block (1 per warp)
#define CAP   192        // candidate buffer per query
#define KMAX  32
#define MMAX  32768
#define GC    27         // grid cells per axis (1728/64)
#define NC    (GC*GC*GC)
#define CSH   6          // log2(cell size 64)
#define BCAP  32         // bucket capacity per cell
#define NEAR2 4096       // 64^2: any point outside cheb<=1 cube has d2 > NEAR2

// ---- device scratch (no allocs allowed) ----
struct Scratch {
    int ovcnt;
    int cellcnt[NC];
};
__device__ Scratch g_scr;            // zeroed by one cudaMemsetAsync per call
__device__ uint2 g_pts[NC * BCAP];   // bucketed: .x = x|y<<16, .y = z|idx<<16
__device__ uint2 g_ov[MMAX];         // overflow (exactness fallback; empty in practice)

__device__ __forceinline__ int cell_of(int x, int y, int z) {
    return (x >> CSH) + GC * (y >> CSH) + GC * GC * (z >> CSH);
}

__device__ __forceinline__ void bin_point(const int* __restrict__ mid,
                                          const int* __restrict__ low,
                                          int i, int M1) {
    const int* s = (i < M1) ? (mid + 3 * i) : (low + 3 * (i - M1));
    int x = s[0], y = s[1], z = s[2];
    int c = cell_of(x, y, z);
    uint2 pt = make_uint2((unsigned)x | ((unsigned)y << 16),
                          (unsigned)z | ((unsigned)i << 16));
    int pos = atomicAdd(&g_scr.cellcnt[c], 1);
    if (pos < BCAP) g_pts[c * BCAP + pos] = pt;
    else            g_ov[atomicAdd(&g_scr.ovcnt, 1)] = pt;
}

// 2 points per thread: two independent atomic->store chains overlap (MLP=2)
__global__ void build_kernel(const int* __restrict__ mid, const int* __restrict__ low,
                             int M1, int M, int half) {
    int i = blockIdx.x * blockDim.x + threadIdx.x;
    if (i >= half) return;
    bin_point(mid, low, i, M1);
    int j = i + half;
    if (j < M) bin_point(mid, low, j, M1);
}

// Exact k-th select (binary search on integer d2), then compact entries with
// d2 <= T to front. Returns T; updates cnt (warp-uniform). Keeps all ties.
__device__ __forceinline__ int warp_prune(uint2* buf, int& cnt, int k, int lane) {
    const unsigned FULL = 0xffffffffu;
    unsigned d2r[CAP / 32], idr[CAP / 32];
#pragma unroll
    for (int s = 0; s < CAP / 32; s++) {
        int i = s * 32 + lane;
        uint2 e = (i < cnt) ? buf[i] : make_uint2(0x7fffffffu, 0u);
        d2r[s] = e.x; idr[s] = e.y;
    }
    unsigned mx = 0;
#pragma unroll
    for (int s = 0; s < CAP / 32; s++) {
        int i = s * 32 + lane;
        if (i < cnt) mx = max(mx, d2r[s]);
    }
    unsigned lo = 0, hi = __reduce_max_sync(FULL, mx);
    while (lo < hi) {
        unsigned mid = (lo + hi) >> 1;
        int c = 0;
#pragma unroll
        for (int s = 0; s < CAP / 32; s++) c += (d2r[s] <= mid) ? 1 : 0;
        c = __reduce_add_sync(FULL, c);
        if (c >= k) hi = mid; else lo = mid + 1;
    }
    unsigned T = lo;
    int base = 0;
#pragma unroll
    for (int s = 0; s < CAP / 32; s++) {
        bool keep = (d2r[s] <= T);
        unsigned m = __ballot_sync(FULL, keep);
        if (keep) buf[base + __popc(m & ((1u << lane) - 1u))] = make_uint2(d2r[s], idr[s]);
        base += __popc(m);
    }
    __syncwarp();
    cnt = base;
    return (int)T;
}

// Balanced segment-union scan (fallback path): dual-batched, ballot append.
// Appends hits with dlo < d2 <= T (dlo excludes already-buffered points).
__device__ __forceinline__ void scan_batch(int ccnt, int cbase, int dlo,
                                           int qx, int qy, int qz,
                                           uint2* bufrow, int* prefrow, int* baserow,
                                           int& cnt, int& T, int kk,
                                           int lane, unsigned lmlt) {
    const unsigned FULL = 0xffffffffu;
    int inc = ccnt;
#pragma unroll
    for (int off = 1; off < 32; off <<= 1) {
        int v = __shfl_up_sync(FULL, inc, off);
        if (lane >= off) inc += v;
    }
    int P = __shfl_sync(FULL, inc, 31);
    if (P == 0) return;
    if (lane == 0) prefrow[0] = 0;
    prefrow[lane + 1] = inc;
    baserow[lane] = cbase - (inc - ccnt);
    __syncwarp();

    const int nb = (P + 31) >> 5;
    for (int it = 0; it < nb; it += 2) {
        int t2a = it * 32 + lane;
        int t2b = t2a + 32;
        bool va = (t2a < P), vb = (t2b < P);
        int ja = 0, jb = 0;
#pragma unroll
        for (int step = 16; step >= 1; step >>= 1) {
            if (prefrow[ja + step] <= t2a) ja += step;
            if (prefrow[jb + step] <= t2b) jb += step;
        }
        uint2 pa, pb;
        if (va) pa = g_pts[baserow[ja] + t2a];
        if (vb) pb = g_pts[baserow[jb] + t2b];
        int d2a = 0, d2b = 0;
        unsigned ia = 0, ib = 0;
        if (va) {
            int dx = qx - (int)(pa.x & 0xffffu);
            int dy = qy - (int)(pa.x >> 16);
            int dz = qz - (int)(pa.y & 0xffffu);
            d2a = dx * dx + dy * dy + dz * dz;
            ia = pa.y >> 16;
        }
        if (vb) {
            int dx = qx - (int)(pb.x & 0xffffu);
            int dy = qy - (int)(pb.x >> 16);
            int dz = qz - (int)(pb.y & 0xffffu);
            d2b = dx * dx + dy * dy + dz * dz;
            ib = pb.y >> 16;
        }
        bool ha = va && (d2a > dlo) && (d2a <= T);
        unsigned ma = __ballot_sync(FULL, ha);
        if (ha) bufrow[cnt + __popc(ma & lmlt)] = make_uint2((unsigned)d2a, ia);
        cnt += __popc(ma);
        bool hb = vb && (d2b > dlo) && (d2b <= T);
        unsigned mb = __ballot_sync(FULL, hb);
        if (hb) bufrow[cnt + __popc(mb & lmlt)] = make_uint2((unsigned)d2b, ib);
        cnt += __popc(mb);
        if (cnt > CAP - 64) T = min(T, warp_prune(bufrow, cnt, kk, lane));
    }
    __syncwarp();
}

struct WarpSmem {
    uint2    buf[CAP];
    int      cbase[32];
    int      ccnt[32];
    int      pref[33];
    int      selidx[KMAX];
    unsigned seld2[KMAX];
    float    wt[KMAX];
};

__global__ __launch_bounds__(128, 10)   // ~48-reg budget: less spill than (128,12)
void knn_query_kernel(const int* __restrict__ qc,
                      const float* __restrict__ midf,
                      const float* __restrict__ lowf,
                      const int* __restrict__ kp,
                      float* __restrict__ out,
                      int N, int M1, int D) {
    __shared__ WarpSmem smarr[QPB];

    const unsigned FULL = 0xffffffffu;
    const int w = threadIdx.x >> 5;
    const int lane = threadIdx.x & 31;
    const unsigned lmlt = (1u << lane) - 1u;
    const int kk = kp ? min(*kp, KMAX) : 24;
    const int ov = g_scr.ovcnt;
    WarpSmem& sm = smarr[w];

    const int q = blockIdx.x * QPB + w;
    if (q >= N) return;                          // whole warp exits together

    const int qx = qc[3 * q], qy = qc[3 * q + 1], qz = qc[3 * q + 2];
    const int qcx = min(qx >> CSH, GC - 1);
    const int qcy = min(qy >> CSH, GC - 1);
    const int qcz = min(qz >> CSH, GC - 1);

    int cnt = 0;

    // ============ PHASE 1 (common): 27 cells (md2-filtered), chunk-of-4 scan ====
    // Proof: every point outside the cheb<=1 cube has axis gap >= 65 => d2 > 4096.
    // A cube cell with md2 > NEAR2 contains no point with d2 <= NEAR2 either.
    // If >= k points pass the d2<=NEAR2 filter, the exact top-k is in the buffer.
    bool p1_ran = false;
    {
        int ccnt = 0, cbase = 0;
        if (lane < 27) {
            int di = lane % 3 - 1;
            int dj = (lane / 3) % 3 - 1;
            int dk = lane / 9 - 1;
            int ci = qcx + di, cj = qcy + dj, ck = qcz + dk;
            if (ci >= 0 && ci < GC && cj >= 0 && cj < GC && ck >= 0 && ck < GC) {
                int lx = ci << CSH, ly = cj << CSH, lz = ck << CSH;
                int mdx = max(0, max(lx - qx, qx - (lx + 63)));
                int mdy = max(0, max(ly - qy, qy - (ly + 63)));
                int mdz = max(0, max(lz - qz, qz - (lz + 63)));
                if (mdx * mdx + mdy * mdy + mdz * mdz <= NEAR2) {
                    int cell = ci + GC * cj + GC * GC * ck;
                    ccnt = min(g_scr.cellcnt[cell], BCAP);
                    cbase = cell * BCAP;
                }
            }
        }
        sm.cbase[lane] = cbase;
        sm.ccnt[lane]  = ccnt;
        int P = __reduce_add_sync(FULL, ccnt);
        if (ov == 0 && P >= kk) {
            p1_ran = true;
            int ch = (ccnt + 3) >> 2;           // 4-point chunks per cell
            int inc = ch;
#pragma unroll
            for (int off = 1; off < 32; off <<= 1) {
                int v = __shfl_up_sync(FULL, inc, off);
                if (lane >= off) inc += v;
            }
            int CH = __shfl_sync(FULL, inc, 31);
            if (lane == 0) sm.pref[0] = 0;
            sm.pref[lane + 1] = inc;
            __syncwarp();

            int T1 = NEAR2;
            for (int c0 = 0; c0 < CH; c0 += 32) {
                int c2 = c0 + lane;
                bool cv = (c2 < CH);
                int c2c = cv ? c2 : 0;
                int j = 0;
#pragma unroll
                for (int step = 16; step >= 1; step >>= 1)
                    if (sm.pref[j + step] <= c2c) j += step;
                int base = sm.cbase[j];
                int cc   = sm.ccnt[j];
                int off4 = (c2c - sm.pref[j]) << 2;
                int nv   = cv ? min(4, cc - off4) : 0;
                uint4 A = make_uint4(0, 0, 0, 0), B = make_uint4(0, 0, 0, 0);
                if (cv) {
                    const uint4* p4 = reinterpret_cast<const uint4*>(&g_pts[base + off4]);
                    A = p4[0];
                    B = p4[1];
                }
                unsigned px[4] = {A.x, A.z, B.x, B.z};
                unsigned pz[4] = {A.y, A.w, B.y, B.w};
#pragma unroll
                for (int u = 0; u < 4; u++) {
                    int d2 = 0;
                    unsigned pidx = 0;
                    bool valid = (u < nv);
                    if (valid) {
                        int dx = qx - (int)(px[u] & 0xffffu);
                        int dy = qy - (int)(px[u] >> 16);
                        int dz = qz - (int)(pz[u] & 0xffffu);
                        d2 = dx * dx + dy * dy + dz * dz;
                        pidx = pz[u] >> 16;
                    }
                    bool hit = valid && (d2 <= T1);
                    unsigned m = __ballot_sync(FULL, hit);
                    if (hit) sm.buf[cnt + __popc(m & lmlt)] =
                                 make_uint2((unsigned)d2, pidx);
                    cnt += __popc(m);
                }
                if (cnt > 64) T1 = min(T1, warp_prune(sm.buf, cnt, kk, lane));
            }
        }
    }

    // ============ FALLBACK (sparse / overflow): complement + shells ============
    if (cnt < kk) {
        int T = 0x7fffffff;
        for (int b = 0; b < ov; b += 32) {
            int i = b + lane;
            bool valid = (i < ov);
            int d2 = 0; unsigned pidx = 0;
            if (valid) {
                uint2 p = g_ov[i];
                int dx = qx - (int)(p.x & 0xffffu);
                int dy = qy - (int)(p.x >> 16);
                int dz = qz - (int)(p.y & 0xffffu);
                d2 = dx * dx + dy * dy + dz * dz;
                pidx = p.y >> 16;
            }
            bool hit = valid && (d2 <= T);
            unsigned m = __ballot_sync(FULL, hit);
            if (hit) sm.buf[cnt + __popc(m & lmlt)] = make_uint2((unsigned)d2, pidx);
            cnt += __popc(m);
            if (cnt > CAP - 32) T = warp_prune(sm.buf, cnt, kk, lane);
        }

        // If phase 1 ran, buffer already holds ALL d2<=NEAR2 points exactly once
        // (cnt < kk <= 32 means no prune fired): append only the complement
        // (d2 > NEAR2) from the cube; shells are disjoint from the cube.
        const int dlo0 = p1_ran ? NEAR2 : -1;
        bool done = false;
        for (int s = 1; s < GC && !done; s++) {
            const int side = 2 * s + 1;
            const int ncube = side * side * side;
            const bool first = (s == 1);
            const int dlo = first ? dlo0 : -1;
            for (int b = 0; b < ncube; b += 32) {
                int t = b + lane;
                int ccnt = 0, cbase = 0;
                if (t < ncube) {
                    int di = t % side - s;
                    int r1 = t / side;
                    int dj = r1 % side - s;
                    int dk = r1 / side - s;
                    int cheb = max(abs(di), max(abs(dj), abs(dk)));
                    int ci = qcx + di, cj = qcy + dj, ck = qcz + dk;
                    if ((first || cheb == s) && ci >= 0 && ci < GC && cj >= 0
                                             && cj < GC && ck >= 0 && ck < GC) {
                        int lx = ci << CSH, ly = cj << CSH, lz = ck << CSH;
                        int mdx = max(0, max(lx - qx, qx - (lx + 63)));
                        int mdy = max(0, max(ly - qy, qy - (ly + 63)));
                        int mdz = max(0, max(lz - qz, qz - (lz + 63)));
                        int md2 = mdx * mdx + mdy * mdy + mdz * mdz;
                        if (md2 <= T) {
                            int cell = ci + GC * cj + GC * GC * ck;
                            ccnt = min(g_scr.cellcnt[cell], BCAP);
                            cbase = cell * BCAP;
                        }
                    }
                }
                scan_batch(ccnt, cbase, dlo, qx, qy, qz, sm.buf, sm.pref,
                           sm.cbase, cnt, T, kk, lane, lmlt);
            }
            if (cnt >= kk) {
                T = warp_prune(sm.buf, cnt, kk, lane);
                int bnd = s << CSH;
                if (bnd * bnd >= T) done = true;
            }
        }
    }

    // ----- final exact top-k by composite key (d2, idx): stable ties -----
    if (cnt > 64) warp_prune(sm.buf, cnt, kk, lane);
    const int kk2 = min(kk, cnt);
    {
        bool v0 = (lane < cnt), v1 = (lane + 32 < cnt);
        uint2 e0 = v0 ? sm.buf[lane]      : make_uint2(0u, 0u);
        uint2 e1 = v1 ? sm.buf[lane + 32] : make_uint2(0u, 0u);
        unsigned mxd2 = __reduce_max_sync(FULL, max(v0 ? e0.x : 0u, v1 ? e1.x : 0u));
        if (cnt <= 64 && mxd2 < (1u << 17)) {
            unsigned k0 = v0 ? ((e0.x << 15) | (e0.y & 0x7fffu)) : 0xffffffffu;
            unsigned k1 = v1 ? ((e1.x << 15) | (e1.y & 0x7fffu)) : 0xffffffffu;
            if (cnt <= 32) {
                int r0 = 0;
                for (int j = 0; j < 32; j++) {
                    unsigned a = __shfl_sync(FULL, k0, j);
                    r0 += (a < k0) ? 1 : 0;
                }
                if (v0 && r0 < kk2) { sm.selidx[r0] = (int)e0.y; sm.seld2[r0] = e0.x; }
            } else {
                int r0 = 0, r1 = 0;
                for (int j = 0; j < 32; j++) {
                    unsigned a = __shfl_sync(FULL, k0, j);
                    unsigned b = __shfl_sync(FULL, k1, j);
                    r0 += ((a < k0) ? 1 : 0) + ((b < k0) ? 1 : 0);
                    r1 += ((a < k1) ? 1 : 0) + ((b < k1) ? 1 : 0);
                }
                if (v0 && r0 < kk2) { sm.selidx[r0] = (int)e0.y; sm.seld2[r0] = e0.x; }
                if (v1 && r1 < kk2) { sm.selidx[r1] = (int)e1.y; sm.seld2[r1] = e1.x; }
            }
        } else {
            for (int i = lane; i < cnt; i += 32) {
                uint2 ei = sm.buf[i];
                int rk = 0;
                for (int j = 0; j < cnt; j++) {
                    uint2 ej = sm.buf[j];
                    rk += (ej.x < ei.x || (ej.x == ei.x && ej.y < ei.y)) ? 1 : 0;
                }
                if (rk < kk2) { sm.selidx[rk] = (int)ei.y; sm.seld2[rk] = ei.x; }
            }
        }
        __syncwarp();
    }

    float wj = 0.0f;
    if (lane < kk2) wj = 1.0f / (1.0f + sqrtf((float)sm.seld2[lane]));
    float tot = wj;
#pragma unroll
    for (int o = 16; o > 0; o >>= 1) tot += __shfl_xor_sync(FULL, tot, o);
    if (lane < kk2) sm.wt[lane] = wj / tot;
    __syncwarp();

    // ----- weighted feature gather (unroll-4 for MLP) -----
    if (D == 128) {
        float4 acc = make_float4(0.f, 0.f, 0.f, 0.f);
        int j = 0;
        for (; j + 4 <= kk2; j += 4) {
            const float* f[4];
            float wt[4];
#pragma unroll
            for (int u = 0; u < 4; u++) {
                int si = sm.selidx[j + u];
                wt[u] = sm.wt[j + u];
                f[u] = (si < M1) ? (midf + (size_t)si * 128)
                                 : (lowf + (size_t)(si - M1) * 128);
            }
            float4 v0 = *(const float4*)(f[0] + lane * 4);
            float4 v1 = *(const float4*)(f[1] + lane * 4);
            float4 v2 = *(const float4*)(f[2] + lane * 4);
            float4 v3 = *(const float4*)(f[3] + lane * 4);
            acc.x += wt[0] * v0.x + wt[1] * v1.x + wt[2] * v2.x + wt[3] * v3.x;
            acc.y += wt[0] * v0.y + wt[1] * v1.y + wt[2] * v2.y + wt[3] * v3.y;
            acc.z += wt[0] * v0.z + wt[1] * v1.z + wt[2] * v2.z + wt[3] * v3.z;
            acc.w += wt[0] * v0.w + wt[1] * v1.w + wt[2] * v2.w + wt[3] * v3.w;
        }
        for (; j < kk2; j++) {
            int   si = sm.selidx[j];
            float wt = sm.wt[j];
            const float* f = (si < M1) ? (midf + (size_t)si * 128)
                                       : (lowf + (size_t)(si - M1) * 128);
            float4 v = *(const float4*)(f + lane * 4);
            acc.x += wt * v.x; acc.y += wt * v.y;
            acc.z += wt * v.z; acc.w += wt * v.w;
        }
        *(float4*)(out + (size_t)q * 128 + lane * 4) = acc;
    } else {
        for (int d = lane; d < D; d += 32) {
            float a = 0.f;
            for (int j = 0; j < kk2; j++) {
                int   si = sm.selidx[j];
                float wt = sm.wt[j];
                const float* f = (si < M1) ? (midf + (size_t)si * D)
                                           : (lowf + (size_t)(si - M1) * D);
                a += wt * f[d];
            }
            out[(size_t)q * D + d] = a;
        }
    }
}

extern "C" void kernel_launch(void* const* d_in, const int* in_sizes, int n_in,
                              void* d_out, int out_size) {
    const int*   qc   = (const int*)d_in[0];
    const int*   midc = (const int*)d_in[1];
    const int*   lowc = (const int*)d_in[2];
    const float* midf = (const float*)d_in[3];
    const float* lowf = (const float*)d_in[4];
    const int*   kp   = (n_in >= 6) ? (const int*)d_in[5] : nullptr;

    const int N  = in_sizes[0] / 3;
    const int M1 = in_sizes[1] / 3;
    const int M2 = in_sizes[2] / 3;
    const int M  = M1 + M2;
    const int D  = (M1 > 0) ? in_sizes[3] / M1 : 128;

    void* scr = nullptr;
    cudaGetSymbolAddress(&scr, g_scr);             // host query, not a stream op
    cudaMemsetAsync(scr, 0, sizeof(Scratch));      // zeroes ovcnt/cellcnt

    const int half = (M + 1) >> 1;
    build_kernel<<<(half + 255) / 256, 256>>>(midc, lowc, M1, M, half);
    knn_query_kernel<<<(N + QPB - 1) / QPB, 128>>>(qc, midf, lowf, kp,
                                                   (float*)d_out, N, M1, D);
}

// round 16
// speedup vs baseline: 1.1875x; 1.0078x over previous
#include <cuda_runtime.h>
#include <stdint.h>

#define QPB   4          // queries per block (1 per warp)
#define CAP   192        // candidate buffer per query
#define KMAX  32
#define MMAX  32768
#define GC    27         // grid cells per axis (1728/64)
#define NC    (GC*GC*GC)
#define CSH   6          // log2(cell size 64)
#define BCAP  32         // bucket capacity per cell
#define NEAR2 4096       // 64^2: any point outside cheb<=1 cube has d2 > NEAR2

// ---- device scratch (no allocs allowed) ----
struct Scratch {
    int ovcnt;
    int cellcnt[NC];
};
__device__ Scratch g_scr;            // zeroed by one cudaMemsetAsync per call
__device__ uint2 g_pts[NC * BCAP];   // bucketed: .x = x|y<<16, .y = z|idx<<16
__device__ uint2 g_ov[MMAX];         // overflow (exactness fallback; empty in practice)

__device__ __forceinline__ int cell_of(int x, int y, int z) {
    return (x >> CSH) + GC * (y >> CSH) + GC * GC * (z >> CSH);
}

__device__ __forceinline__ void bin_point(const int* __restrict__ mid,
                                          const int* __restrict__ low,
                                          int i, int M1) {
    const int* s = (i < M1) ? (mid + 3 * i) : (low + 3 * (i - M1));
    int x = s[0], y = s[1], z = s[2];
    int c = cell_of(x, y, z);
    uint2 pt = make_uint2((unsigned)x | ((unsigned)y << 16),
                          (unsigned)z | ((unsigned)i << 16));
    int pos = atomicAdd(&g_scr.cellcnt[c], 1);
    if (pos < BCAP) g_pts[c * BCAP + pos] = pt;
    else            g_ov[atomicAdd(&g_scr.ovcnt, 1)] = pt;
}

// 2 points per thread: two independent atomic->store chains overlap (MLP=2)
__global__ void build_kernel(const int* __restrict__ mid, const int* __restrict__ low,
                             int M1, int M, int half) {
    int i = blockIdx.x * blockDim.x + threadIdx.x;
    if (i >= half) return;
    bin_point(mid, low, i, M1);
    int j = i + half;
    if (j < M) bin_point(mid, low, j, M1);
}

// Exact k-th select (binary search on integer d2), then compact entries with
// d2 <= T to front. Returns T; updates cnt (warp-uniform). Keeps all ties.
__device__ __forceinline__ int warp_prune(uint2* buf, int& cnt, int k, int lane) {
    const unsigned FULL = 0xffffffffu;
    unsigned d2r[CAP / 32], idr[CAP / 32];
#pragma unroll
    for (int s = 0; s < CAP / 32; s++) {
        int i = s * 32 + lane;
        uint2 e = (i < cnt) ? buf[i] : make_uint2(0x7fffffffu, 0u);
        d2r[s] = e.x; idr[s] = e.y;
    }
    unsigned mx = 0;
#pragma unroll
    for (int s = 0; s < CAP / 32; s++) {
        int i = s * 32 + lane;
        if (i < cnt) mx = max(mx, d2r[s]);
    }
    unsigned lo = 0, hi = __reduce_max_sync(FULL, mx);
    while (lo < hi) {
        unsigned mid = (lo + hi) >> 1;
        int c = 0;
#pragma unroll
        for (int s = 0; s < CAP / 32; s++) c += (d2r[s] <= mid) ? 1 : 0;
        c = __reduce_add_sync(FULL, c);
        if (c >= k) hi = mid; else lo = mid + 1;
    }
    unsigned T = lo;
    int base = 0;
#pragma unroll
    for (int s = 0; s < CAP / 32; s++) {
        bool keep = (d2r[s] <= T);
        unsigned m = __ballot_sync(FULL, keep);
        if (keep) buf[base + __popc(m & ((1u << lane) - 1u))] = make_uint2(d2r[s], idr[s]);
        base += __popc(m);
    }
    __syncwarp();
    cnt = base;
    return (int)T;
}

// Balanced segment-union scan (fallback path): dual-batched, ballot append.
// Appends hits with dlo < d2 <= T (dlo excludes already-buffered points).
__device__ __forceinline__ void scan_batch(int ccnt, int cbase, int dlo,
                                           int qx, int qy, int qz,
                                           uint2* bufrow, int* prefrow, int* baserow,
                                           int& cnt, int& T, int kk,
                                           int lane, unsigned lmlt) {
    const unsigned FULL = 0xffffffffu;
    int inc = ccnt;
#pragma unroll
    for (int off = 1; off < 32; off <<= 1) {
        int v = __shfl_up_sync(FULL, inc, off);
        if (lane >= off) inc += v;
    }
    int P = __shfl_sync(FULL, inc, 31);
    if (P == 0) return;
    if (lane == 0) prefrow[0] = 0;
    prefrow[lane + 1] = inc;
    baserow[lane] = cbase - (inc - ccnt);
    __syncwarp();

    const int nb = (P + 31) >> 5;
    for (int it = 0; it < nb; it += 2) {
        int t2a = it * 32 + lane;
        int t2b = t2a + 32;
        bool va = (t2a < P), vb = (t2b < P);
        int ja = 0, jb = 0;
#pragma unroll
        for (int step = 16; step >= 1; step >>= 1) {
            if (prefrow[ja + step] <= t2a) ja += step;
            if (prefrow[jb + step] <= t2b) jb += step;
        }
        uint2 pa, pb;
        if (va) pa = g_pts[baserow[ja] + t2a];
        if (vb) pb = g_pts[baserow[jb] + t2b];
        int d2a = 0, d2b = 0;
        unsigned ia = 0, ib = 0;
        if (va) {
            int dx = qx - (int)(pa.x & 0xffffu);
            int dy = qy - (int)(pa.x >> 16);
            int dz = qz - (int)(pa.y & 0xffffu);
            d2a = dx * dx + dy * dy + dz * dz;
            ia = pa.y >> 16;
        }
        if (vb) {
            int dx = qx - (int)(pb.x & 0xffffu);
            int dy = qy - (int)(pb.x >> 16);
            int dz = qz - (int)(pb.y & 0xffffu);
            d2b = dx * dx + dy * dy + dz * dz;
            ib = pb.y >> 16;
        }
        bool ha = va && (d2a > dlo) && (d2a <= T);
        unsigned ma = __ballot_sync(FULL, ha);
        if (ha) bufrow[cnt + __popc(ma & lmlt)] = make_uint2((unsigned)d2a, ia);
        cnt += __popc(ma);
        bool hb = vb && (d2b > dlo) && (d2b <= T);
        unsigned mb = __ballot_sync(FULL, hb);
        if (hb) bufrow[cnt + __popc(mb & lmlt)] = make_uint2((unsigned)d2b, ib);
        cnt += __popc(mb);
        if (cnt > CAP - 64) T = min(T, warp_prune(bufrow, cnt, kk, lane));
    }
    __syncwarp();
}

struct WarpSmem {
    uint2    buf[CAP];
    int      cbase[32];
    int      ccnt[32];
    int      pref[33];
    int      selidx[KMAX];
    unsigned seld2[KMAX];
    float    wt[KMAX];
    unsigned long long fb[KMAX];     // precomputed feature-row pointers
};

__global__ __launch_bounds__(128, 12)   // proven best: occupancy > spill cost
void knn_query_kernel(const int* __restrict__ qc,
                      const float* __restrict__ midf,
                      const float* __restrict__ lowf,
                      const int* __restrict__ kp,
                      float* __restrict__ out,
                      int N, int M1, int D) {
    __shared__ WarpSmem smarr[QPB];

    const unsigned FULL = 0xffffffffu;
    const int w = threadIdx.x >> 5;
    const int lane = threadIdx.x & 31;
    const unsigned lmlt = (1u << lane) - 1u;
    const int kk = kp ? min(*kp, KMAX) : 24;
    const int ov = g_scr.ovcnt;
    WarpSmem& sm = smarr[w];

    const int q = blockIdx.x * QPB + w;
    if (q >= N) return;                          // whole warp exits together

    const int qx = qc[3 * q], qy = qc[3 * q + 1], qz = qc[3 * q + 2];
    const int qcx = min(qx >> CSH, GC - 1);
    const int qcy = min(qy >> CSH, GC - 1);
    const int qcz = min(qz >> CSH, GC - 1);

    int cnt = 0;

    // ============ PHASE 1 (common): 27 cells (md2-filtered), chunk-of-4 scan ====
    // Proof: every point outside the cheb<=1 cube has axis gap >= 65 => d2 > 4096.
    // A cube cell with md2 > NEAR2 contains no point with d2 <= NEAR2 either.
    // If >= k points pass the d2<=NEAR2 filter, the exact top-k is in the buffer.
    bool p1_ran = false;
    {
        int ccnt = 0, cbase = 0;
        if (lane < 27) {
            int di = lane % 3 - 1;
            int dj = (lane / 3) % 3 - 1;
            int dk = lane / 9 - 1;
            int ci = qcx + di, cj = qcy + dj, ck = qcz + dk;
            if (ci >= 0 && ci < GC && cj >= 0 && cj < GC && ck >= 0 && ck < GC) {
                int lx = ci << CSH, ly = cj << CSH, lz = ck << CSH;
                int mdx = max(0, max(lx - qx, qx - (lx + 63)));
                int mdy = max(0, max(ly - qy, qy - (ly + 63)));
                int mdz = max(0, max(lz - qz, qz - (lz + 63)));
                if (mdx * mdx + mdy * mdy + mdz * mdz <= NEAR2) {
                    int cell = ci + GC * cj + GC * GC * ck;
                    ccnt = min(g_scr.cellcnt[cell], BCAP);
                    cbase = cell * BCAP;
                }
            }
        }
        sm.cbase[lane] = cbase;
        sm.ccnt[lane]  = ccnt;
        int P = __reduce_add_sync(FULL, ccnt);
        if (ov == 0 && P >= kk) {
            p1_ran = true;
            int ch = (ccnt + 3) >> 2;           // 4-point chunks per cell
            int inc = ch;
#pragma unroll
            for (int off = 1; off < 32; off <<= 1) {
                int v = __shfl_up_sync(FULL, inc, off);
                if (lane >= off) inc += v;
            }
            int CH = __shfl_sync(FULL, inc, 31);
            if (lane == 0) sm.pref[0] = 0;
            sm.pref[lane + 1] = inc;
            __syncwarp();

            int T1 = NEAR2;
            for (int c0 = 0; c0 < CH; c0 += 32) {
                int c2 = c0 + lane;
                bool cv = (c2 < CH);
                int c2c = cv ? c2 : 0;
                int j = 0;
#pragma unroll
                for (int step = 16; step >= 1; step >>= 1)
                    if (sm.pref[j + step] <= c2c) j += step;
                int base = sm.cbase[j];
                int cc   = sm.ccnt[j];
                int off4 = (c2c - sm.pref[j]) << 2;
                int nv   = cv ? min(4, cc - off4) : 0;
                uint4 A = make_uint4(0, 0, 0, 0), B = make_uint4(0, 0, 0, 0);
                if (cv) {
                    const uint4* p4 = reinterpret_cast<const uint4*>(&g_pts[base + off4]);
                    A = p4[0];
                    B = p4[1];
                }
                unsigned px[4] = {A.x, A.z, B.x, B.z};
                unsigned pz[4] = {A.y, A.w, B.y, B.w};
#pragma unroll
                for (int u = 0; u < 4; u++) {
                    int d2 = 0;
                    unsigned pidx = 0;
                    bool valid = (u < nv);
                    if (valid) {
                        int dx = qx - (int)(px[u] & 0xffffu);
                        int dy = qy - (int)(px[u] >> 16);
                        int dz = qz - (int)(pz[u] & 0xffffu);
                        d2 = dx * dx + dy * dy + dz * dz;
                        pidx = pz[u] >> 16;
                    }
                    bool hit = valid && (d2 <= T1);
                    unsigned m = __ballot_sync(FULL, hit);
                    if (hit) sm.buf[cnt + __popc(m & lmlt)] =
                                 make_uint2((unsigned)d2, pidx);
                    cnt += __popc(m);
                }
                if (cnt > 64) T1 = min(T1, warp_prune(sm.buf, cnt, kk, lane));
            }
        }
    }

    // ============ FALLBACK (sparse / overflow): complement + shells ============
    if (cnt < kk) {
        int T = 0x7fffffff;
        for (int b = 0; b < ov; b += 32) {
            int i = b + lane;
            bool valid = (i < ov);
            int d2 = 0; unsigned pidx = 0;
            if (valid) {
                uint2 p = g_ov[i];
                int dx = qx - (int)(p.x & 0xffffu);
                int dy = qy - (int)(p.x >> 16);
                int dz = qz - (int)(p.y & 0xffffu);
                d2 = dx * dx + dy * dy + dz * dz;
                pidx = p.y >> 16;
            }
            bool hit = valid && (d2 <= T);
            unsigned m = __ballot_sync(FULL, hit);
            if (hit) sm.buf[cnt + __popc(m & lmlt)] = make_uint2((unsigned)d2, pidx);
            cnt += __popc(m);
            if (cnt > CAP - 32) T = warp_prune(sm.buf, cnt, kk, lane);
        }

        // If phase 1 ran, buffer already holds ALL d2<=NEAR2 points exactly once
        // (cnt < kk <= 32 means no prune fired): append only the complement
        // (d2 > NEAR2) from the cube; shells are disjoint from the cube.
        const int dlo0 = p1_ran ? NEAR2 : -1;
        bool done = false;
        for (int s = 1; s < GC && !done; s++) {
            const int side = 2 * s + 1;
            const int ncube = side * side * side;
            const bool first = (s == 1);
            const int dlo = first ? dlo0 : -1;
            for (int b = 0; b < ncube; b += 32) {
                int t = b + lane;
                int ccnt = 0, cbase = 0;
                if (t < ncube) {
                    int di = t % side - s;
                    int r1 = t / side;
                    int dj = r1 % side - s;
                    int dk = r1 / side - s;
                    int cheb = max(abs(di), max(abs(dj), abs(dk)));
                    int ci = qcx + di, cj = qcy + dj, ck = qcz + dk;
                    if ((first || cheb == s) && ci >= 0 && ci < GC && cj >= 0
                                             && cj < GC && ck >= 0 && ck < GC) {
                        int lx = ci << CSH, ly = cj << CSH, lz = ck << CSH;
                        int mdx = max(0, max(lx - qx, qx - (lx + 63)));
                        int mdy = max(0, max(ly - qy, qy - (ly + 63)));
                        int mdz = max(0, max(lz - qz, qz - (lz + 63)));
                        int md2 = mdx * mdx + mdy * mdy + mdz * mdz;
                        if (md2 <= T) {
                            int cell = ci + GC * cj + GC * GC * ck;
                            ccnt = min(g_scr.cellcnt[cell], BCAP);
                            cbase = cell * BCAP;
                        }
                    }
                }
                scan_batch(ccnt, cbase, dlo, qx, qy, qz, sm.buf, sm.pref,
                           sm.cbase, cnt, T, kk, lane, lmlt);
            }
            if (cnt >= kk) {
                T = warp_prune(sm.buf, cnt, kk, lane);
                int bnd = s << CSH;
                if (bnd * bnd >= T) done = true;
            }
        }
    }

    // ----- final exact top-k by composite key (d2, idx): stable ties -----
    if (cnt > 64) warp_prune(sm.buf, cnt, kk, lane);
    const int kk2 = min(kk, cnt);
    {
        bool v0 = (lane < cnt), v1 = (lane + 32 < cnt);
        uint2 e0 = v0 ? sm.buf[lane]      : make_uint2(0u, 0u);
        uint2 e1 = v1 ? sm.buf[lane + 32] : make_uint2(0u, 0u);
        unsigned mxd2 = __reduce_max_sync(FULL, max(v0 ? e0.x : 0u, v1 ? e1.x : 0u));
        if (cnt <= 64 && mxd2 < (1u << 17)) {
            unsigned k0 = v0 ? ((e0.x << 15) | (e0.y & 0x7fffu)) : 0xffffffffu;
            unsigned k1 = v1 ? ((e1.x << 15) | (e1.y & 0x7fffu)) : 0xffffffffu;
            if (cnt <= 32) {
                int r0 = 0;
                for (int j = 0; j < 32; j++) {
                    unsigned a = __shfl_sync(FULL, k0, j);
                    r0 += (a < k0) ? 1 : 0;
                }
                if (v0 && r0 < kk2) { sm.selidx[r0] = (int)e0.y; sm.seld2[r0] = e0.x; }
            } else {
                int r0 = 0, r1 = 0;
                for (int j = 0; j < 32; j++) {
                    unsigned a = __shfl_sync(FULL, k0, j);
                    unsigned b = __shfl_sync(FULL, k1, j);
                    r0 += ((a < k0) ? 1 : 0) + ((b < k0) ? 1 : 0);
                    r1 += ((a < k1) ? 1 : 0) + ((b < k1) ? 1 : 0);
                }
                if (v0 && r0 < kk2) { sm.selidx[r0] = (int)e0.y; sm.seld2[r0] = e0.x; }
                if (v1 && r1 < kk2) { sm.selidx[r1] = (int)e1.y; sm.seld2[r1] = e1.x; }
            }
        } else {
            for (int i = lane; i < cnt; i += 32) {
                uint2 ei = sm.buf[i];
                int rk = 0;
                for (int j = 0; j < cnt; j++) {
                    uint2 ej = sm.buf[j];
                    rk += (ej.x < ei.x || (ej.x == ei.x && ej.y < ei.y)) ? 1 : 0;
                }
                if (rk < kk2) { sm.selidx[rk] = (int)ei.y; sm.seld2[rk] = ei.x; }
            }
        }
        __syncwarp();
    }

    // weights + per-neighbor feature-row pointer (computed once by lane==rank)
    float wj = 0.0f;
    if (lane < kk2) wj = 1.0f / (1.0f + sqrtf((float)sm.seld2[lane]));
    float tot = wj;
#pragma unroll
    for (int o = 16; o > 0; o >>= 1) tot += __shfl_xor_sync(FULL, tot, o);
    if (lane < kk2) {
        sm.wt[lane] = wj / tot;
        int si = sm.selidx[lane];
        const float* f = (si < M1) ? (midf + (size_t)si * D)
                                   : (lowf + (size_t)(si - M1) * D);
        sm.fb[lane] = (unsigned long long)f;
    }
    __syncwarp();

    // ----- weighted feature gather (unroll-4 for MLP; pointers from smem) -----
    if (D == 128) {
        float4 acc = make_float4(0.f, 0.f, 0.f, 0.f);
        int j = 0;
        for (; j + 4 <= kk2; j += 4) {
            const float* f0 = (const float*)sm.fb[j];
            const float* f1 = (const float*)sm.fb[j + 1];
            const float* f2 = (const float*)sm.fb[j + 2];
            const float* f3 = (const float*)sm.fb[j + 3];
            float w0 = sm.wt[j], w1 = sm.wt[j + 1];
            float w2 = sm.wt[j + 2], w3 = sm.wt[j + 3];
            float4 v0 = *(const float4*)(f0 + lane * 4);
            float4 v1 = *(const float4*)(f1 + lane * 4);
            float4 v2 = *(const float4*)(f2 + lane * 4);
            float4 v3 = *(const float4*)(f3 + lane * 4);
            acc.x += w0 * v0.x + w1 * v1.x + w2 * v2.x + w3 * v3.x;
            acc.y += w0 * v0.y + w1 * v1.y + w2 * v2.y + w3 * v3.y;
            acc.z += w0 * v0.z + w1 * v1.z + w2 * v2.z + w3 * v3.z;
            acc.w += w0 * v0.w + w1 * v1.w + w2 * v2.w + w3 * v3.w;
        }
        for (; j < kk2; j++) {
            const float* f = (const float*)sm.fb[j];
            float wt = sm.wt[j];
            float4 v = *(const float4*)(f + lane * 4);
            acc.x += wt * v.x; acc.y += wt * v.y;
            acc.z += wt * v.z; acc.w += wt * v.w;
        }
        *(float4*)(out + (size_t)q * 128 + lane * 4) = acc;
    } else {
        for (int d = lane; d < D; d += 32) {
            float a = 0.f;
            for (int j = 0; j < kk2; j++) {
                const float* f = (const float*)sm.fb[j];
                a += sm.wt[j] * f[d];
            }
            out[(size_t)q * D + d] = a;
        }
    }
}

extern "C" void kernel_launch(void* const* d_in, const int* in_sizes, int n_in,
                              void* d_out, int out_size) {
    const int*   qc   = (const int*)d_in[0];
    const int*   midc = (const int*)d_in[1];
    const int*   lowc = (const int*)d_in[2];
    const float* midf = (const float*)d_in[3];
    const float* lowf = (const float*)d_in[4];
    const int*   kp   = (n_in >= 6) ? (const int*)d_in[5] : nullptr;

    const int N  = in_sizes[0] / 3;
    const int M1 = in_sizes[1] / 3;
    const int M2 = in_sizes[2] / 3;
    const int M  = M1 + M2;
    const int D  = (M1 > 0) ? in_sizes[3] / M1 : 128;

    void* scr = nullptr;
    cudaGetSymbolAddress(&scr, g_scr);             // host query, not a stream op
    cudaMemsetAsync(scr, 0, sizeof(Scratch));      // zeroes ovcnt/cellcnt

    const int half = (M + 1) >> 1;
    build_kernel<<<(half + 255) / 256, 256>>>(midc, lowc, M1, M, half);
    knn_query_kernel<<<(N + QPB - 1) / QPB, 128>>>(qc, midf, lowf, kp,
                                                   (float*)d_out, N, M1, D);
}